// round 15
// baseline (speedup 1.0000x reference)
#include <cuda_runtime.h>
#include <cuda_bf16.h>
#include <math.h>
#include <stdint.h>

// Shapes (fixed): B=1, MSA=64, L=256, D=512, H=8, DH=64, HM = H*MSA = 512
#define HM_ 512
#define L_ 256
#define DH_ 64

// Scratch in device globals (allocation-free rule).
__device__ float g_q[HM_ * L_ * DH_];
__device__ float g_k[HM_ * L_ * DH_];
__device__ float g_v[HM_ * L_ * DH_];
__device__ float g_z[HM_ * L_ * DH_];
__device__ float g_S[HM_ * L_ * L_];

// ---------------------------------------------------------------------------
// helpers
// ---------------------------------------------------------------------------
__device__ __forceinline__ uint32_t smem_u32(const void* p) {
    uint32_t a;
    asm("{ .reg .u64 t; cvta.to.shared.u64 t, %1; cvt.u32.u64 %0, t; }" : "=r"(a) : "l"(p));
    return a;
}
__device__ __forceinline__ void ldm_x4(uint32_t* r, uint32_t addr) {
    asm volatile("ldmatrix.sync.aligned.m8n8.x4.shared.b16 {%0,%1,%2,%3}, [%4];"
                 : "=r"(r[0]), "=r"(r[1]), "=r"(r[2]), "=r"(r[3]) : "r"(addr));
}
__device__ __forceinline__ void ldm_x4_trans(uint32_t* r, uint32_t addr) {
    asm volatile("ldmatrix.sync.aligned.m8n8.x4.trans.shared.b16 {%0,%1,%2,%3}, [%4];"
                 : "=r"(r[0]), "=r"(r[1]), "=r"(r[2]), "=r"(r[3]) : "r"(addr));
}
__device__ __forceinline__ void mma_bf16(float* d, const uint32_t* a, const uint32_t* b) {
    asm volatile(
        "mma.sync.aligned.m16n8k16.row.col.f32.bf16.bf16.f32 "
        "{%0,%1,%2,%3}, {%4,%5,%6,%7}, {%8,%9}, {%0,%1,%2,%3};"
        : "+f"(d[0]), "+f"(d[1]), "+f"(d[2]), "+f"(d[3])
        : "r"(a[0]), "r"(a[1]), "r"(a[2]), "r"(a[3]), "r"(b[0]), "r"(b[1]));
}
// fp32 float4 -> hi/lo bf16x4 stored to smem
__device__ __forceinline__ void cvt_store(float4 v, __nv_bfloat16* ph, __nv_bfloat16* pl) {
    __nv_bfloat16 h0 = __float2bfloat16_rn(v.x), h1 = __float2bfloat16_rn(v.y),
                  h2 = __float2bfloat16_rn(v.z), h3 = __float2bfloat16_rn(v.w);
    __nv_bfloat16 l0 = __float2bfloat16_rn(v.x - __bfloat162float(h0)),
                  l1 = __float2bfloat16_rn(v.y - __bfloat162float(h1)),
                  l2 = __float2bfloat16_rn(v.z - __bfloat162float(h2)),
                  l3 = __float2bfloat16_rn(v.w - __bfloat162float(h3));
    __nv_bfloat162 hp0(h0, h1), hp1(h2, h3), lp0(l0, l1), lp1(l2, l3);
    *(uint2*)ph = make_uint2(*(uint32_t*)&hp0, *(uint32_t*)&hp1);
    *(uint2*)pl = make_uint2(*(uint32_t*)&lp0, *(uint32_t*)&lp1);
}

// ---------------------------------------------------------------------------
// Kernel 1: QKV projection via mma.sync bf16 (hi/lo 3-pass, fp32 accum).
// Reads fp32 x/W directly, hi/lo split on the fly (split kernels removed —
// fp32 reads cost identical bytes to pre-split hi+lo bf16 reads).
// ---------------------------------------------------------------------------
__global__ __launch_bounds__(256) void proj_mma_kernel(
    const float* __restrict__ x,
    const float* __restrict__ Wq,
    const float* __restrict__ Wk,
    const float* __restrict__ Wv)
{
    __shared__ __nv_bfloat16 sAh[128][40];
    __shared__ __nv_bfloat16 sAl[128][40];
    __shared__ __nv_bfloat16 sBh[128][40];
    __shared__ __nv_bfloat16 sBl[128][40];

    int tid = threadIdx.x;
    int lane = tid & 31, wid = tid >> 5;
    int wr = wid >> 2, wc = wid & 3;

    int n0 = blockIdx.x * 128;
    int m0 = blockIdx.y * 128;
    int wsel = blockIdx.z;

    const float* W = (wsel == 0) ? Wq : (wsel == 1) ? Wk : Wv;
    float* Y = (wsel == 0) ? g_q : (wsel == 1) ? g_k : g_v;

    float acc[4][4][4];
    #pragma unroll
    for (int a = 0; a < 4; a++)
        #pragma unroll
        for (int b = 0; b < 4; b++)
            #pragma unroll
            for (int c = 0; c < 4; c++) acc[a][b][c] = 0.f;

    int rowA = wr * 64 + (lane & 15);
    int colA = (lane >> 4) * 8;
    uint32_t aAh = smem_u32(&sAh[rowA][colA]);
    uint32_t aAl = smem_u32(&sAl[rowA][colA]);
    int rowB = wc * 32 + (lane & 7) + ((lane >> 4) << 3);
    int colB = ((lane >> 3) & 1) * 8;
    uint32_t aBh = smem_u32(&sBh[rowB][colB]);
    uint32_t aBl = smem_u32(&sBl[rowB][colB]);

    for (int kt = 0; kt < 16; kt++) {
        int k0 = kt * 32;
        // A: x rows 128 x 32 fp32 = 1024 float4 chunks; B: W same. 4 iters each.
        #pragma unroll
        for (int it = 0; it < 4; it++) {
            int idx = tid + 256 * it;
            int row = idx >> 3, cg = (idx & 7) * 4;
            float4 va = *(const float4*)(x + (size_t)(m0 + row) * 512 + k0 + cg);
            cvt_store(va, &sAh[row][cg], &sAl[row][cg]);
            float4 vb = *(const float4*)(W + (size_t)(n0 + row) * 512 + k0 + cg);
            cvt_store(vb, &sBh[row][cg], &sBl[row][cg]);
        }
        __syncthreads();

        #pragma unroll
        for (int ks = 0; ks < 2; ks++) {
            uint32_t ah[4][4], al[4][4], bh[4][2], bl[4][2];
            #pragma unroll
            for (int mt = 0; mt < 4; mt++) {
                uint32_t off = (uint32_t)(mt * 16 * 40 + ks * 16) * 2;
                ldm_x4(ah[mt], aAh + off);
                ldm_x4(al[mt], aAl + off);
            }
            #pragma unroll
            for (int np = 0; np < 2; np++) {
                uint32_t off = (uint32_t)(np * 16 * 40 + ks * 16) * 2;
                uint32_t t[4];
                ldm_x4(t, aBh + off);
                bh[np * 2][0] = t[0]; bh[np * 2][1] = t[1];
                bh[np * 2 + 1][0] = t[2]; bh[np * 2 + 1][1] = t[3];
                ldm_x4(t, aBl + off);
                bl[np * 2][0] = t[0]; bl[np * 2][1] = t[1];
                bl[np * 2 + 1][0] = t[2]; bl[np * 2 + 1][1] = t[3];
            }
            #pragma unroll
            for (int mt = 0; mt < 4; mt++) {
                #pragma unroll
                for (int nt = 0; nt < 4; nt++) {
                    mma_bf16(acc[mt][nt], ah[mt], bh[nt]);
                    mma_bf16(acc[mt][nt], ah[mt], bl[nt]);
                    mma_bf16(acc[mt][nt], al[mt], bh[nt]);
                }
            }
        }
        __syncthreads();
    }

    #pragma unroll
    for (int mt = 0; mt < 4; mt++) {
        #pragma unroll
        for (int nt = 0; nt < 4; nt++) {
            int m_lo = m0 + wr * 64 + mt * 16 + (lane >> 2);
            int n = n0 + wc * 32 + nt * 8 + (lane & 3) * 2;
            int h = n >> 6, d = n & 63;
            int msa0 = m_lo >> 8, i0 = m_lo & 255;
            float* p0 = Y + ((size_t)(h * 64 + msa0) * 256 + i0) * 64 + d;
            *(float2*)p0 = make_float2(acc[mt][nt][0], acc[mt][nt][1]);
            int m_hi = m_lo + 8;
            int msa1 = m_hi >> 8, i1 = m_hi & 255;
            float* p1 = Y + ((size_t)(h * 64 + msa1) * 256 + i1) * 64 + d;
            *(float2*)p1 = make_float2(acc[mt][nt][2], acc[mt][nt][3]);
        }
    }
}

// ---------------------------------------------------------------------------
// Kernel 2a: e1 = scale*(q @ k^T) -> S.  Per hm, 128i x 128j blocks, K=64.
// ---------------------------------------------------------------------------
__global__ __launch_bounds__(256) void e1_mma_kernel()
{
    __shared__ __nv_bfloat16 sAh[128][40];
    __shared__ __nv_bfloat16 sAl[128][40];
    __shared__ __nv_bfloat16 sBh[128][40];
    __shared__ __nv_bfloat16 sBl[128][40];

    int tid = threadIdx.x;
    int lane = tid & 31, wid = tid >> 5;
    int wr = wid >> 2, wc = wid & 3;

    int j0 = blockIdx.x * 128;
    int i0 = blockIdx.y * 128;
    int hm = blockIdx.z;
    const float* qb = g_q + (size_t)hm * (L_ * DH_);
    const float* kb = g_k + (size_t)hm * (L_ * DH_);

    float acc[4][4][4];
    #pragma unroll
    for (int a = 0; a < 4; a++)
        #pragma unroll
        for (int b = 0; b < 4; b++)
            #pragma unroll
            for (int c = 0; c < 4; c++) acc[a][b][c] = 0.f;

    int rowA = wr * 64 + (lane & 15);
    int colA = (lane >> 4) * 8;
    uint32_t aAh = smem_u32(&sAh[rowA][colA]);
    uint32_t aAl = smem_u32(&sAl[rowA][colA]);
    int rowB = wc * 32 + (lane & 7) + ((lane >> 4) << 3);
    int colB = ((lane >> 3) & 1) * 8;
    uint32_t aBh = smem_u32(&sBh[rowB][colB]);
    uint32_t aBl = smem_u32(&sBl[rowB][colB]);

    for (int kt = 0; kt < 2; kt++) {
        int k0 = kt * 32;
        #pragma unroll
        for (int it = 0; it < 4; it++) {
            int idx = tid + 256 * it;
            int row = idx >> 3, cg = (idx & 7) * 4;
            float4 va = *(const float4*)(qb + (size_t)(i0 + row) * 64 + k0 + cg);
            cvt_store(va, &sAh[row][cg], &sAl[row][cg]);
            float4 vb = *(const float4*)(kb + (size_t)(j0 + row) * 64 + k0 + cg);
            cvt_store(vb, &sBh[row][cg], &sBl[row][cg]);
        }
        __syncthreads();

        #pragma unroll
        for (int ks = 0; ks < 2; ks++) {
            uint32_t ah[4][4], al[4][4], bh[4][2], bl[4][2];
            #pragma unroll
            for (int mt = 0; mt < 4; mt++) {
                uint32_t off = (uint32_t)(mt * 16 * 40 + ks * 16) * 2;
                ldm_x4(ah[mt], aAh + off);
                ldm_x4(al[mt], aAl + off);
            }
            #pragma unroll
            for (int np = 0; np < 2; np++) {
                uint32_t off = (uint32_t)(np * 16 * 40 + ks * 16) * 2;
                uint32_t t[4];
                ldm_x4(t, aBh + off);
                bh[np * 2][0] = t[0]; bh[np * 2][1] = t[1];
                bh[np * 2 + 1][0] = t[2]; bh[np * 2 + 1][1] = t[3];
                ldm_x4(t, aBl + off);
                bl[np * 2][0] = t[0]; bl[np * 2][1] = t[1];
                bl[np * 2 + 1][0] = t[2]; bl[np * 2 + 1][1] = t[3];
            }
            #pragma unroll
            for (int mt = 0; mt < 4; mt++) {
                #pragma unroll
                for (int nt = 0; nt < 4; nt++) {
                    mma_bf16(acc[mt][nt], ah[mt], bh[nt]);
                    mma_bf16(acc[mt][nt], ah[mt], bl[nt]);
                    mma_bf16(acc[mt][nt], al[mt], bh[nt]);
                }
            }
        }
        __syncthreads();
    }

    const float scale = 0.125f;
    float* Sb = g_S + (size_t)hm * (L_ * L_);
    #pragma unroll
    for (int mt = 0; mt < 4; mt++) {
        #pragma unroll
        for (int nt = 0; nt < 4; nt++) {
            int row = i0 + wr * 64 + mt * 16 + (lane >> 2);
            int col = j0 + wc * 32 + nt * 8 + (lane & 3) * 2;
            float* p = Sb + (size_t)row * 256 + col;
            *(float2*)p = make_float2(acc[mt][nt][0] * scale, acc[mt][nt][1] * scale);
            *(float2*)(p + 8 * 256) = make_float2(acc[mt][nt][2] * scale, acc[mt][nt][3] * scale);
        }
    }
}

// ---------------------------------------------------------------------------
// Kernel 2b: S = softmax(S_e1 + scale*(q_i @ aK[i]^T)), fused softmax, PLUS
// fused z2 phase: z[hm0..+63, i, :] = alpha_tile @ aV[i]  (plain write).
// Tile = 64 hm x 256 j (full rows) at fixed i. grid (hm-tiles=8, i=256).
// ---------------------------------------------------------------------------
__global__ __launch_bounds__(256) void e2_softmax_z2_kernel(
    const float* __restrict__ aK, const float* __restrict__ aV)
{
    __shared__ __nv_bfloat16 sAh[64][40];
    __shared__ __nv_bfloat16 sAl[64][40];
    __shared__ __nv_bfloat16 sBh[256][40];
    __shared__ __nv_bfloat16 sBl[256][40];
    __shared__ __nv_bfloat16 sVh[32][72];
    __shared__ __nv_bfloat16 sVl[32][72];
    __shared__ float sRed[2][4][64];

    int tid = threadIdx.x;
    int lane = tid & 31, wid = tid >> 5;
    int wr = wid >> 2, wc = wid & 3;

    int hm0 = blockIdx.x * 64;
    int i = blockIdx.y;
    const float* aKb = aK + (size_t)i * (L_ * DH_);

    float acc[2][8][4];
    #pragma unroll
    for (int a = 0; a < 2; a++)
        #pragma unroll
        for (int b = 0; b < 8; b++)
            #pragma unroll
            for (int c = 0; c < 4; c++) acc[a][b][c] = 0.f;

    int rowA = wr * 32 + (lane & 15);
    int colA = (lane >> 4) * 8;
    uint32_t aAh = smem_u32(&sAh[rowA][colA]);
    uint32_t aAl = smem_u32(&sAl[rowA][colA]);
    int rowB = wc * 64 + (lane & 7) + ((lane >> 4) << 3);
    int colB = ((lane >> 3) & 1) * 8;
    uint32_t aBh = smem_u32(&sBh[rowB][colB]);
    uint32_t aBl = smem_u32(&sBl[rowB][colB]);

    for (int kt = 0; kt < 2; kt++) {
        int k0 = kt * 32;
        #pragma unroll
        for (int it = 0; it < 2; it++) {
            int idx = tid + 256 * it;
            int row = idx >> 3, cg = (idx & 7) * 4;
            float4 va = *(const float4*)(g_q + (size_t)(hm0 + row) * (L_ * DH_) + (size_t)i * 64 + k0 + cg);
            cvt_store(va, &sAh[row][cg], &sAl[row][cg]);
        }
        #pragma unroll
        for (int it = 0; it < 8; it++) {
            int idx = tid + 256 * it;
            int row = idx >> 3, cg = (idx & 7) * 4;
            float4 vb = *(const float4*)(aKb + (size_t)row * 64 + k0 + cg);
            cvt_store(vb, &sBh[row][cg], &sBl[row][cg]);
        }
        __syncthreads();

        #pragma unroll
        for (int ks = 0; ks < 2; ks++) {
            uint32_t ah[2][4], al[2][4], bh[8][2], bl[8][2];
            #pragma unroll
            for (int mt = 0; mt < 2; mt++) {
                uint32_t off = (uint32_t)(mt * 16 * 40 + ks * 16) * 2;
                ldm_x4(ah[mt], aAh + off);
                ldm_x4(al[mt], aAl + off);
            }
            #pragma unroll
            for (int np = 0; np < 4; np++) {
                uint32_t off = (uint32_t)(np * 16 * 40 + ks * 16) * 2;
                uint32_t t[4];
                ldm_x4(t, aBh + off);
                bh[np * 2][0] = t[0]; bh[np * 2][1] = t[1];
                bh[np * 2 + 1][0] = t[2]; bh[np * 2 + 1][1] = t[3];
                ldm_x4(t, aBl + off);
                bl[np * 2][0] = t[0]; bl[np * 2][1] = t[1];
                bl[np * 2 + 1][0] = t[2]; bl[np * 2 + 1][1] = t[3];
            }
            #pragma unroll
            for (int mt = 0; mt < 2; mt++) {
                #pragma unroll
                for (int nt = 0; nt < 8; nt++) {
                    mma_bf16(acc[mt][nt], ah[mt], bh[nt]);
                    mma_bf16(acc[mt][nt], ah[mt], bl[nt]);
                    mma_bf16(acc[mt][nt], al[mt], bh[nt]);
                }
            }
        }
        __syncthreads();
    }

    // ---- Fused epilogue: e = S_e1 + scale*acc, then row softmax over j ----
    const float scale = 0.125f;
    #pragma unroll
    for (int mt = 0; mt < 2; mt++) {
        #pragma unroll
        for (int nt = 0; nt < 8; nt++) {
            int row = hm0 + wr * 32 + mt * 16 + (lane >> 2);
            int col = wc * 64 + nt * 8 + (lane & 3) * 2;
            const float* p = g_S + (size_t)row * (L_ * L_) + (size_t)i * 256 + col;
            float2 s0 = *(const float2*)p;
            float2 s1 = *(const float2*)(p + (size_t)8 * (L_ * L_));
            acc[mt][nt][0] = acc[mt][nt][0] * scale + s0.x;
            acc[mt][nt][1] = acc[mt][nt][1] * scale + s0.y;
            acc[mt][nt][2] = acc[mt][nt][2] * scale + s1.x;
            acc[mt][nt][3] = acc[mt][nt][3] * scale + s1.y;
        }
    }

    int rl[2][2];
    #pragma unroll
    for (int mt = 0; mt < 2; mt++)
        #pragma unroll
        for (int h = 0; h < 2; h++)
            rl[mt][h] = wr * 32 + mt * 16 + h * 8 + (lane >> 2);

    float mx[2][2];
    #pragma unroll
    for (int mt = 0; mt < 2; mt++)
        #pragma unroll
        for (int h = 0; h < 2; h++) {
            float m = -1e30f;
            #pragma unroll
            for (int nt = 0; nt < 8; nt++)
                m = fmaxf(m, fmaxf(acc[mt][nt][h * 2], acc[mt][nt][h * 2 + 1]));
            mx[mt][h] = m;
        }
    #pragma unroll
    for (int off = 1; off <= 2; off <<= 1) {
        #pragma unroll
        for (int mt = 0; mt < 2; mt++)
            #pragma unroll
            for (int h = 0; h < 2; h++)
                mx[mt][h] = fmaxf(mx[mt][h], __shfl_xor_sync(0xffffffffu, mx[mt][h], off));
    }
    if ((lane & 3) == 0) {
        #pragma unroll
        for (int mt = 0; mt < 2; mt++)
            #pragma unroll
            for (int h = 0; h < 2; h++)
                sRed[0][wc][rl[mt][h]] = mx[mt][h];
    }
    __syncthreads();
    float mfull[2][2];
    #pragma unroll
    for (int mt = 0; mt < 2; mt++)
        #pragma unroll
        for (int h = 0; h < 2; h++)
            mfull[mt][h] = fmaxf(fmaxf(sRed[0][0][rl[mt][h]], sRed[0][1][rl[mt][h]]),
                                 fmaxf(sRed[0][2][rl[mt][h]], sRed[0][3][rl[mt][h]]));

    float sm[2][2] = {{0.f, 0.f}, {0.f, 0.f}};
    #pragma unroll
    for (int mt = 0; mt < 2; mt++) {
        #pragma unroll
        for (int nt = 0; nt < 8; nt++) {
            #pragma unroll
            for (int h = 0; h < 2; h++) {
                float e0 = __expf(acc[mt][nt][h * 2] - mfull[mt][h]);
                float e1v = __expf(acc[mt][nt][h * 2 + 1] - mfull[mt][h]);
                acc[mt][nt][h * 2] = e0;
                acc[mt][nt][h * 2 + 1] = e1v;
                sm[mt][h] += e0 + e1v;
            }
        }
    }
    #pragma unroll
    for (int off = 1; off <= 2; off <<= 1) {
        #pragma unroll
        for (int mt = 0; mt < 2; mt++)
            #pragma unroll
            for (int h = 0; h < 2; h++)
                sm[mt][h] += __shfl_xor_sync(0xffffffffu, sm[mt][h], off);
    }
    if ((lane & 3) == 0) {
        #pragma unroll
        for (int mt = 0; mt < 2; mt++)
            #pragma unroll
            for (int h = 0; h < 2; h++)
                sRed[1][wc][rl[mt][h]] = sm[mt][h];
    }
    __syncthreads();
    float inv[2][2];
    #pragma unroll
    for (int mt = 0; mt < 2; mt++)
        #pragma unroll
        for (int h = 0; h < 2; h++) {
            float s = (sRed[1][0][rl[mt][h]] + sRed[1][1][rl[mt][h]]) +
                      (sRed[1][2][rl[mt][h]] + sRed[1][3][rl[mt][h]]);
            inv[mt][h] = 1.0f / s;
        }

    // write normalized probs to g_S
    #pragma unroll
    for (int mt = 0; mt < 2; mt++) {
        #pragma unroll
        for (int nt = 0; nt < 8; nt++) {
            int row = hm0 + wr * 32 + mt * 16 + (lane >> 2);
            int col = wc * 64 + nt * 8 + (lane & 3) * 2;
            float* p = g_S + (size_t)row * (L_ * L_) + (size_t)i * 256 + col;
            *(float2*)p = make_float2(acc[mt][nt][0] * inv[mt][0], acc[mt][nt][1] * inv[mt][0]);
            *(float2*)(p + (size_t)8 * (L_ * L_)) =
                make_float2(acc[mt][nt][2] * inv[mt][1], acc[mt][nt][3] * inv[mt][1]);
        }
    }
    __syncthreads();   // gmem writes visible block-wide before phase 2 reads

    // ---- Phase 2 (fused z2): z[hm0..+63, i, :] = alpha_tile @ aV[i] ----
    const float* aVb = aV + (size_t)i * (L_ * DH_);
    float accz[4][4];
    #pragma unroll
    for (int b = 0; b < 4; b++)
        #pragma unroll
        for (int c = 0; c < 4; c++) accz[b][c] = 0.f;

    int wrz = wid >> 1;
    int wdz = wid & 1;
    int rowAz = wrz * 16 + (lane & 15);
    uint32_t aAzh = smem_u32(&sAh[rowAz][colA]);
    uint32_t aAzl = smem_u32(&sAl[rowAz][colA]);
    int rowVt = lane & 15;
    int colVt = wdz * 32 + ((lane >> 4) << 3);
    uint32_t aVha = smem_u32(&sVh[rowVt][colVt]);
    uint32_t aVla = smem_u32(&sVl[rowVt][colVt]);

    for (int jc = 0; jc < 8; jc++) {
        int k0 = jc * 32;
        #pragma unroll
        for (int it = 0; it < 2; it++) {
            int idx = tid + 256 * it;
            int row = idx >> 3, cg = (idx & 7) * 4;
            float4 va = *(const float4*)(g_S + (size_t)(hm0 + row) * (L_ * L_) + (size_t)i * 256 + k0 + cg);
            cvt_store(va, &sAh[row][cg], &sAl[row][cg]);
        }
        #pragma unroll
        for (int it = 0; it < 2; it++) {
            int idx = tid + 256 * it;
            int jr = idx >> 4, cg = (idx & 15) * 4;
            float4 vb = *(const float4*)(aVb + (size_t)(k0 + jr) * 64 + cg);
            cvt_store(vb, &sVh[jr][cg], &sVl[jr][cg]);
        }
        __syncthreads();

        #pragma unroll
        for (int ks = 0; ks < 2; ks++) {
            uint32_t ah[4], al4[4], bh[4][2], bl[4][2];
            uint32_t offA = (uint32_t)(ks * 16) * 2;
            ldm_x4(ah, aAzh + offA);
            ldm_x4(al4, aAzl + offA);
            #pragma unroll
            for (int nn = 0; nn < 2; nn++) {
                uint32_t off = (uint32_t)(ks * 16 * 72 + nn * 16) * 2;
                uint32_t t[4];
                ldm_x4_trans(t, aVha + off);
                bh[nn * 2][0] = t[0]; bh[nn * 2][1] = t[1];
                bh[nn * 2 + 1][0] = t[2]; bh[nn * 2 + 1][1] = t[3];
                ldm_x4_trans(t, aVla + off);
                bl[nn * 2][0] = t[0]; bl[nn * 2][1] = t[1];
                bl[nn * 2 + 1][0] = t[2]; bl[nn * 2 + 1][1] = t[3];
            }
            #pragma unroll
            for (int nt = 0; nt < 4; nt++) {
                mma_bf16(accz[nt], ah, bh[nt]);
                mma_bf16(accz[nt], ah, bl[nt]);
                mma_bf16(accz[nt], al4, bh[nt]);
            }
        }
        __syncthreads();
    }

    #pragma unroll
    for (int nt = 0; nt < 4; nt++) {
        int row = hm0 + wrz * 16 + (lane >> 2);
        int col = wdz * 32 + nt * 8 + (lane & 3) * 2;
        float* p = g_z + (size_t)row * (L_ * DH_) + (size_t)i * 64 + col;
        *(float2*)p = make_float2(accz[nt][0], accz[nt][1]);
        *(float2*)(p + (size_t)8 * (L_ * DH_)) = make_float2(accz[nt][2], accz[nt][3]);
    }
}

// ---------------------------------------------------------------------------
// Kernel 4a: z += alpha @ v (RMW on top of fused-z2 output).
// grid (i-tiles=2, hm=512).
// ---------------------------------------------------------------------------
__global__ __launch_bounds__(256) void z1_mma_kernel()
{
    __shared__ __nv_bfloat16 sAh[128][40];
    __shared__ __nv_bfloat16 sAl[128][40];
    __shared__ __nv_bfloat16 sBh[32][72];
    __shared__ __nv_bfloat16 sBl[32][72];

    int tid = threadIdx.x;
    int lane = tid & 31, wid = tid >> 5;
    int wi = wid >> 1, wd = wid & 1;

    int i0 = blockIdx.x * 128;
    int hm = blockIdx.y;
    const float* Ab = g_S + (size_t)hm * (L_ * L_);
    const float* Bb = g_v + (size_t)hm * (L_ * DH_);

    float acc[2][4][4];
    #pragma unroll
    for (int a = 0; a < 2; a++)
        #pragma unroll
        for (int b = 0; b < 4; b++)
            #pragma unroll
            for (int c = 0; c < 4; c++) acc[a][b][c] = 0.f;

    int rowA = wi * 32 + (lane & 15);
    int colA = (lane >> 4) * 8;
    uint32_t aAh = smem_u32(&sAh[rowA][colA]);
    uint32_t aAl = smem_u32(&sAl[rowA][colA]);
    int rowBt = lane & 15;
    int colBt = wd * 32 + ((lane >> 4) << 3);
    uint32_t aBh = smem_u32(&sBh[rowBt][colBt]);
    uint32_t aBl = smem_u32(&sBl[rowBt][colBt]);

    for (int jt = 0; jt < 8; jt++) {
        int k0 = jt * 32;
        #pragma unroll
        for (int it = 0; it < 4; it++) {
            int idx = tid + 256 * it;
            int row = idx >> 3, cg = (idx & 7) * 4;
            float4 va = *(const float4*)(Ab + (size_t)(i0 + row) * 256 + k0 + cg);
            cvt_store(va, &sAh[row][cg], &sAl[row][cg]);
        }
        {
            int jr = tid >> 4, cg = (tid & 15) * 4;
            float4 vb = *(const float4*)(Bb + (size_t)(k0 + jr) * 64 + cg);
            cvt_store(vb, &sBh[jr][cg], &sBl[jr][cg]);
            int idx2 = tid + 256;
            int jr2 = idx2 >> 4, cg2 = (idx2 & 15) * 4;
            float4 vb2 = *(const float4*)(Bb + (size_t)(k0 + jr2) * 64 + cg2);
            cvt_store(vb2, &sBh[jr2][cg2], &sBl[jr2][cg2]);
        }
        __syncthreads();

        #pragma unroll
        for (int ks = 0; ks < 2; ks++) {
            uint32_t ah[2][4], al[2][4], bh[4][2], bl[4][2];
            #pragma unroll
            for (int mt = 0; mt < 2; mt++) {
                uint32_t off = (uint32_t)(mt * 16 * 40 + ks * 16) * 2;
                ldm_x4(ah[mt], aAh + off);
                ldm_x4(al[mt], aAl + off);
            }
            #pragma unroll
            for (int nn = 0; nn < 2; nn++) {
                uint32_t off = (uint32_t)(ks * 16 * 72 + nn * 16) * 2;
                uint32_t t[4];
                ldm_x4_trans(t, aBh + off);
                bh[nn * 2][0] = t[0]; bh[nn * 2][1] = t[1];
                bh[nn * 2 + 1][0] = t[2]; bh[nn * 2 + 1][1] = t[3];
                ldm_x4_trans(t, aBl + off);
                bl[nn * 2][0] = t[0]; bl[nn * 2][1] = t[1];
                bl[nn * 2 + 1][0] = t[2]; bl[nn * 2 + 1][1] = t[3];
            }
            #pragma unroll
            for (int mt = 0; mt < 2; mt++) {
                #pragma unroll
                for (int nt = 0; nt < 4; nt++) {
                    mma_bf16(acc[mt][nt], ah[mt], bh[nt]);
                    mma_bf16(acc[mt][nt], ah[mt], bl[nt]);
                    mma_bf16(acc[mt][nt], al[mt], bh[nt]);
                }
            }
        }
        __syncthreads();
    }

    float* Zb = g_z + (size_t)hm * (L_ * DH_);
    #pragma unroll
    for (int mt = 0; mt < 2; mt++) {
        #pragma unroll
        for (int nt = 0; nt < 4; nt++) {
            int row = i0 + wi * 32 + mt * 16 + (lane >> 2);
            int col = wd * 32 + nt * 8 + (lane & 3) * 2;
            float* p = Zb + (size_t)row * 64 + col;
            float2 o = *(float2*)p;
            o.x += acc[mt][nt][0]; o.y += acc[mt][nt][1];
            *(float2*)p = o;
            float* p2 = p + 8 * 64;
            float2 o2 = *(float2*)p2;
            o2.x += acc[mt][nt][2]; o2.y += acc[mt][nt][3];
            *(float2*)p2 = o2;
        }
    }
}

// ---------------------------------------------------------------------------
// Kernel 5: out[i, h*64+d] = sum_m z[(h*64+m), i, d]
// ---------------------------------------------------------------------------
__global__ __launch_bounds__(512) void reduce_kernel(float* __restrict__ out)
{
    int i = blockIdx.x;
    int e = threadIdx.x;
    int h = e >> 6, d = e & 63;
    const float* p = g_z + (h * 64) * (L_ * DH_) + i * DH_ + d;
    float s = 0.f;
    #pragma unroll 8
    for (int m = 0; m < 64; m++) s += p[m * (L_ * DH_)];
    out[i * 512 + e] = s;
}

// ---------------------------------------------------------------------------
extern "C" void kernel_launch(void* const* d_in, const int* in_sizes, int n_in,
                              void* d_out, int out_size)
{
    const float* x  = (const float*)d_in[0];
    const float* Wq = (const float*)d_in[1];
    const float* Wk = (const float*)d_in[2];
    const float* Wv = (const float*)d_in[3];
    const float* aK = (const float*)d_in[4];
    const float* aV = (const float*)d_in[5];
    float* out = (float*)d_out;

    proj_mma_kernel     <<<dim3(4, 128, 3), 256>>>(x, Wq, Wk, Wv);
    e1_mma_kernel       <<<dim3(2, 2, 512), 256>>>();
    e2_softmax_z2_kernel<<<dim3(8, 256), 256>>>(aK, aV);
    z1_mma_kernel       <<<dim3(2, 512), 256>>>();
    reduce_kernel       <<<dim3(L_), 512>>>(out);
}

// round 16
// speedup vs baseline: 1.1978x; 1.1978x over previous
#include <cuda_runtime.h>
#include <cuda_bf16.h>
#include <math.h>
#include <stdint.h>

// Shapes (fixed): B=1, MSA=64, L=256, D=512, H=8, DH=64, HM = H*MSA = 512
#define HM_ 512
#define L_ 256
#define DH_ 64

// Scratch in device globals (allocation-free rule).
__device__ float g_q[HM_ * L_ * DH_];
__device__ float g_k[HM_ * L_ * DH_];
__device__ float g_v[HM_ * L_ * DH_];
__device__ float g_z[HM_ * L_ * DH_];
__device__ float g_S[HM_ * L_ * L_];

// bf16 hi/lo splits for tensor-core projection (pre-split: proj loader stays
// a pure 16B copy -> cp.async compatible; round-15 showed on-the-fly cvt in
// proj's 16-iteration loop regresses)
__device__ __nv_bfloat16 g_xhi[16384 * 512];
__device__ __nv_bfloat16 g_xlo[16384 * 512];
__device__ __nv_bfloat16 g_whi[3 * 512 * 512];
__device__ __nv_bfloat16 g_wlo[3 * 512 * 512];

// ---------------------------------------------------------------------------
// helpers
// ---------------------------------------------------------------------------
__device__ __forceinline__ uint32_t smem_u32(const void* p) {
    uint32_t a;
    asm("{ .reg .u64 t; cvta.to.shared.u64 t, %1; cvt.u32.u64 %0, t; }" : "=r"(a) : "l"(p));
    return a;
}
__device__ __forceinline__ void ldm_x4(uint32_t* r, uint32_t addr) {
    asm volatile("ldmatrix.sync.aligned.m8n8.x4.shared.b16 {%0,%1,%2,%3}, [%4];"
                 : "=r"(r[0]), "=r"(r[1]), "=r"(r[2]), "=r"(r[3]) : "r"(addr));
}
__device__ __forceinline__ void ldm_x4_trans(uint32_t* r, uint32_t addr) {
    asm volatile("ldmatrix.sync.aligned.m8n8.x4.trans.shared.b16 {%0,%1,%2,%3}, [%4];"
                 : "=r"(r[0]), "=r"(r[1]), "=r"(r[2]), "=r"(r[3]) : "r"(addr));
}
__device__ __forceinline__ void mma_bf16(float* d, const uint32_t* a, const uint32_t* b) {
    asm volatile(
        "mma.sync.aligned.m16n8k16.row.col.f32.bf16.bf16.f32 "
        "{%0,%1,%2,%3}, {%4,%5,%6,%7}, {%8,%9}, {%0,%1,%2,%3};"
        : "+f"(d[0]), "+f"(d[1]), "+f"(d[2]), "+f"(d[3])
        : "r"(a[0]), "r"(a[1]), "r"(a[2]), "r"(a[3]), "r"(b[0]), "r"(b[1]));
}
__device__ __forceinline__ void cp_async16(uint32_t dst, const void* src) {
    asm volatile("cp.async.cg.shared.global [%0], [%1], 16;" :: "r"(dst), "l"(src) : "memory");
}
__device__ __forceinline__ void cp_async_commit() {
    asm volatile("cp.async.commit_group;" ::: "memory");
}
// fp32 float4 -> hi/lo bf16x4 stored to smem
__device__ __forceinline__ void cvt_store(float4 v, __nv_bfloat16* ph, __nv_bfloat16* pl) {
    __nv_bfloat16 h0 = __float2bfloat16_rn(v.x), h1 = __float2bfloat16_rn(v.y),
                  h2 = __float2bfloat16_rn(v.z), h3 = __float2bfloat16_rn(v.w);
    __nv_bfloat16 l0 = __float2bfloat16_rn(v.x - __bfloat162float(h0)),
                  l1 = __float2bfloat16_rn(v.y - __bfloat162float(h1)),
                  l2 = __float2bfloat16_rn(v.z - __bfloat162float(h2)),
                  l3 = __float2bfloat16_rn(v.w - __bfloat162float(h3));
    __nv_bfloat162 hp0(h0, h1), hp1(h2, h3), lp0(l0, l1), lp1(l2, l3);
    *(uint2*)ph = make_uint2(*(uint32_t*)&hp0, *(uint32_t*)&hp1);
    *(uint2*)pl = make_uint2(*(uint32_t*)&lp0, *(uint32_t*)&lp1);
}

// ---------------------------------------------------------------------------
// Kernel 0: split fp32 -> bf16 hi + lo (projection inputs)
// ---------------------------------------------------------------------------
__global__ __launch_bounds__(256) void split_kernel(
    const float* __restrict__ src, __nv_bfloat16* __restrict__ hi,
    __nv_bfloat16* __restrict__ lo, int n)
{
    int idx = (blockIdx.x * 256 + threadIdx.x) * 4;
    if (idx >= n) return;
    float4 v = *(const float4*)(src + idx);
    cvt_store(v, hi + idx, lo + idx);
}

// ---------------------------------------------------------------------------
// Kernel 1: QKV projection via mma.sync bf16 (hi/lo 3-pass, fp32 accum).
// cp.async double-buffered: stage k+1 copies fly during stage k MMAs.
// Dynamic smem: 2 stages x (4 arrays x 128 x 40 bf16) = 80 KB.
// ---------------------------------------------------------------------------
#define PRJ_ARR   10240                    // 128*40*2 bytes per array
#define PRJ_AH    0
#define PRJ_AL    (1 * PRJ_ARR)
#define PRJ_BH    (2 * PRJ_ARR)
#define PRJ_BL    (3 * PRJ_ARR)
#define PRJ_STAGE (4 * PRJ_ARR)            // 40960
#define PRJ_SMEM_TOTAL (2 * PRJ_STAGE)     // 81920

__global__ __launch_bounds__(256) void proj_mma_kernel()
{
    extern __shared__ char psmem[];
    uint32_t sb = smem_u32(psmem);

    int tid = threadIdx.x;
    int lane = tid & 31, wid = tid >> 5;
    int wr = wid >> 2, wc = wid & 3;

    int n0 = blockIdx.x * 128;
    int m0 = blockIdx.y * 128;
    int wsel = blockIdx.z;

    const __nv_bfloat16* Bhg = g_whi + (size_t)wsel * 512 * 512;
    const __nv_bfloat16* Blg = g_wlo + (size_t)wsel * 512 * 512;
    float* Y = (wsel == 0) ? g_q : (wsel == 1) ? g_k : g_v;

    float acc[4][4][4];
    #pragma unroll
    for (int a = 0; a < 4; a++)
        #pragma unroll
        for (int b = 0; b < 4; b++)
            #pragma unroll
            for (int c = 0; c < 4; c++) acc[a][b][c] = 0.f;

    // per-thread copy coords: 2 chunks of 16B per array per stage
    int lrow[2], lcg[2];
    uint32_t lbyte[2];
    #pragma unroll
    for (int it = 0; it < 2; it++) {
        int idx = tid + 256 * it;
        lrow[it] = idx >> 2;
        lcg[it] = (idx & 3) * 8;
        lbyte[it] = (uint32_t)(lrow[it] * 40 + lcg[it]) * 2;
    }

    // ldmatrix base offsets (within a stage)
    int rowA = wr * 64 + (lane & 15);
    int colA = (lane >> 4) * 8;
    uint32_t offAh = PRJ_AH + (uint32_t)(rowA * 40 + colA) * 2;
    uint32_t offAl = PRJ_AL + (uint32_t)(rowA * 40 + colA) * 2;
    int rowB = wc * 32 + (lane & 7) + ((lane >> 4) << 3);
    int colB = ((lane >> 3) & 1) * 8;
    uint32_t offBh = PRJ_BH + (uint32_t)(rowB * 40 + colB) * 2;
    uint32_t offBl = PRJ_BL + (uint32_t)(rowB * 40 + colB) * 2;

    // prologue: issue stage 0
    {
        uint32_t s0 = sb;
        #pragma unroll
        for (int it = 0; it < 2; it++) {
            cp_async16(s0 + PRJ_AH + lbyte[it], g_xhi + (size_t)(m0 + lrow[it]) * 512 + lcg[it]);
            cp_async16(s0 + PRJ_AL + lbyte[it], g_xlo + (size_t)(m0 + lrow[it]) * 512 + lcg[it]);
            cp_async16(s0 + PRJ_BH + lbyte[it], Bhg + (size_t)(n0 + lrow[it]) * 512 + lcg[it]);
            cp_async16(s0 + PRJ_BL + lbyte[it], Blg + (size_t)(n0 + lrow[it]) * 512 + lcg[it]);
        }
        cp_async_commit();
    }

    for (int kt = 0; kt < 16; kt++) {
        // issue next stage while current copies/MMAs proceed
        if (kt < 15) {
            int k0 = (kt + 1) * 32;
            uint32_t sn = sb + ((kt + 1) & 1) * PRJ_STAGE;
            #pragma unroll
            for (int it = 0; it < 2; it++) {
                cp_async16(sn + PRJ_AH + lbyte[it], g_xhi + (size_t)(m0 + lrow[it]) * 512 + k0 + lcg[it]);
                cp_async16(sn + PRJ_AL + lbyte[it], g_xlo + (size_t)(m0 + lrow[it]) * 512 + k0 + lcg[it]);
                cp_async16(sn + PRJ_BH + lbyte[it], Bhg + (size_t)(n0 + lrow[it]) * 512 + k0 + lcg[it]);
                cp_async16(sn + PRJ_BL + lbyte[it], Blg + (size_t)(n0 + lrow[it]) * 512 + k0 + lcg[it]);
            }
            cp_async_commit();
            asm volatile("cp.async.wait_group 1;" ::: "memory");  // stage kt complete
        } else {
            asm volatile("cp.async.wait_group 0;" ::: "memory");
        }
        __syncthreads();

        uint32_t st = sb + (kt & 1) * PRJ_STAGE;
        #pragma unroll
        for (int ks = 0; ks < 2; ks++) {
            uint32_t ah[4][4], al[4][4], bh[4][2], bl[4][2];
            #pragma unroll
            for (int mt = 0; mt < 4; mt++) {
                uint32_t off = (uint32_t)(mt * 16 * 40 + ks * 16) * 2;
                ldm_x4(ah[mt], st + offAh + off);
                ldm_x4(al[mt], st + offAl + off);
            }
            #pragma unroll
            for (int np = 0; np < 2; np++) {
                uint32_t off = (uint32_t)(np * 16 * 40 + ks * 16) * 2;
                uint32_t t[4];
                ldm_x4(t, st + offBh + off);
                bh[np * 2][0] = t[0]; bh[np * 2][1] = t[1];
                bh[np * 2 + 1][0] = t[2]; bh[np * 2 + 1][1] = t[3];
                ldm_x4(t, st + offBl + off);
                bl[np * 2][0] = t[0]; bl[np * 2][1] = t[1];
                bl[np * 2 + 1][0] = t[2]; bl[np * 2 + 1][1] = t[3];
            }
            #pragma unroll
            for (int mt = 0; mt < 4; mt++) {
                #pragma unroll
                for (int nt = 0; nt < 4; nt++) {
                    mma_bf16(acc[mt][nt], ah[mt], bh[nt]);
                    mma_bf16(acc[mt][nt], ah[mt], bl[nt]);
                    mma_bf16(acc[mt][nt], al[mt], bh[nt]);
                }
            }
        }
        __syncthreads();   // all reads of stage kt done before it is overwritten
    }

    // Epilogue: scatter into head-split layout [(h*64+msa)][i][d]
    #pragma unroll
    for (int mt = 0; mt < 4; mt++) {
        #pragma unroll
        for (int nt = 0; nt < 4; nt++) {
            int m_lo = m0 + wr * 64 + mt * 16 + (lane >> 2);
            int n = n0 + wc * 32 + nt * 8 + (lane & 3) * 2;
            int h = n >> 6, d = n & 63;
            int msa0 = m_lo >> 8, i0 = m_lo & 255;
            float* p0 = Y + ((size_t)(h * 64 + msa0) * 256 + i0) * 64 + d;
            *(float2*)p0 = make_float2(acc[mt][nt][0], acc[mt][nt][1]);
            int m_hi = m_lo + 8;
            int msa1 = m_hi >> 8, i1 = m_hi & 255;
            float* p1 = Y + ((size_t)(h * 64 + msa1) * 256 + i1) * 64 + d;
            *(float2*)p1 = make_float2(acc[mt][nt][2], acc[mt][nt][3]);
        }
    }
}

// ---------------------------------------------------------------------------
// Kernel 2a: e1 = scale*(q @ k^T) -> S.  Per hm, 128i x 128j blocks, K=64.
// ---------------------------------------------------------------------------
__global__ __launch_bounds__(256) void e1_mma_kernel()
{
    __shared__ __nv_bfloat16 sAh[128][40];
    __shared__ __nv_bfloat16 sAl[128][40];
    __shared__ __nv_bfloat16 sBh[128][40];
    __shared__ __nv_bfloat16 sBl[128][40];

    int tid = threadIdx.x;
    int lane = tid & 31, wid = tid >> 5;
    int wr = wid >> 2, wc = wid & 3;

    int j0 = blockIdx.x * 128;
    int i0 = blockIdx.y * 128;
    int hm = blockIdx.z;
    const float* qb = g_q + (size_t)hm * (L_ * DH_);
    const float* kb = g_k + (size_t)hm * (L_ * DH_);

    float acc[4][4][4];
    #pragma unroll
    for (int a = 0; a < 4; a++)
        #pragma unroll
        for (int b = 0; b < 4; b++)
            #pragma unroll
            for (int c = 0; c < 4; c++) acc[a][b][c] = 0.f;

    int rowA = wr * 64 + (lane & 15);
    int colA = (lane >> 4) * 8;
    uint32_t aAh = smem_u32(&sAh[rowA][colA]);
    uint32_t aAl = smem_u32(&sAl[rowA][colA]);
    int rowB = wc * 32 + (lane & 7) + ((lane >> 4) << 3);
    int colB = ((lane >> 3) & 1) * 8;
    uint32_t aBh = smem_u32(&sBh[rowB][colB]);
    uint32_t aBl = smem_u32(&sBl[rowB][colB]);

    for (int kt = 0; kt < 2; kt++) {
        int k0 = kt * 32;
        #pragma unroll
        for (int it = 0; it < 4; it++) {
            int idx = tid + 256 * it;
            int row = idx >> 3, cg = (idx & 7) * 4;
            float4 va = *(const float4*)(qb + (size_t)(i0 + row) * 64 + k0 + cg);
            cvt_store(va, &sAh[row][cg], &sAl[row][cg]);
            float4 vb = *(const float4*)(kb + (size_t)(j0 + row) * 64 + k0 + cg);
            cvt_store(vb, &sBh[row][cg], &sBl[row][cg]);
        }
        __syncthreads();

        #pragma unroll
        for (int ks = 0; ks < 2; ks++) {
            uint32_t ah[4][4], al[4][4], bh[4][2], bl[4][2];
            #pragma unroll
            for (int mt = 0; mt < 4; mt++) {
                uint32_t off = (uint32_t)(mt * 16 * 40 + ks * 16) * 2;
                ldm_x4(ah[mt], aAh + off);
                ldm_x4(al[mt], aAl + off);
            }
            #pragma unroll
            for (int np = 0; np < 2; np++) {
                uint32_t off = (uint32_t)(np * 16 * 40 + ks * 16) * 2;
                uint32_t t[4];
                ldm_x4(t, aBh + off);
                bh[np * 2][0] = t[0]; bh[np * 2][1] = t[1];
                bh[np * 2 + 1][0] = t[2]; bh[np * 2 + 1][1] = t[3];
                ldm_x4(t, aBl + off);
                bl[np * 2][0] = t[0]; bl[np * 2][1] = t[1];
                bl[np * 2 + 1][0] = t[2]; bl[np * 2 + 1][1] = t[3];
            }
            #pragma unroll
            for (int mt = 0; mt < 4; mt++) {
                #pragma unroll
                for (int nt = 0; nt < 4; nt++) {
                    mma_bf16(acc[mt][nt], ah[mt], bh[nt]);
                    mma_bf16(acc[mt][nt], ah[mt], bl[nt]);
                    mma_bf16(acc[mt][nt], al[mt], bh[nt]);
                }
            }
        }
        __syncthreads();
    }

    const float scale = 0.125f;
    float* Sb = g_S + (size_t)hm * (L_ * L_);
    #pragma unroll
    for (int mt = 0; mt < 4; mt++) {
        #pragma unroll
        for (int nt = 0; nt < 4; nt++) {
            int row = i0 + wr * 64 + mt * 16 + (lane >> 2);
            int col = j0 + wc * 32 + nt * 8 + (lane & 3) * 2;
            float* p = Sb + (size_t)row * 256 + col;
            *(float2*)p = make_float2(acc[mt][nt][0] * scale, acc[mt][nt][1] * scale);
            *(float2*)(p + 8 * 256) = make_float2(acc[mt][nt][2] * scale, acc[mt][nt][3] * scale);
        }
    }
}

// ---------------------------------------------------------------------------
// Kernel 2b: S = softmax(S_e1 + scale*(q_i @ aK[i]^T)), fused softmax, PLUS
// fused z2 phase: z[hm0..+63, i, :] = alpha_tile @ aV[i]  (plain write).
// Tile = 64 hm x 256 j (full rows) at fixed i. grid (hm-tiles=8, i=256).
// ---------------------------------------------------------------------------
__global__ __launch_bounds__(256) void e2_softmax_z2_kernel(
    const float* __restrict__ aK, const float* __restrict__ aV)
{
    __shared__ __nv_bfloat16 sAh[64][40];
    __shared__ __nv_bfloat16 sAl[64][40];
    __shared__ __nv_bfloat16 sBh[256][40];
    __shared__ __nv_bfloat16 sBl[256][40];
    __shared__ __nv_bfloat16 sVh[32][72];
    __shared__ __nv_bfloat16 sVl[32][72];
    __shared__ float sRed[2][4][64];

    int tid = threadIdx.x;
    int lane = tid & 31, wid = tid >> 5;
    int wr = wid >> 2, wc = wid & 3;

    int hm0 = blockIdx.x * 64;
    int i = blockIdx.y;
    const float* aKb = aK + (size_t)i * (L_ * DH_);

    float acc[2][8][4];
    #pragma unroll
    for (int a = 0; a < 2; a++)
        #pragma unroll
        for (int b = 0; b < 8; b++)
            #pragma unroll
            for (int c = 0; c < 4; c++) acc[a][b][c] = 0.f;

    int rowA = wr * 32 + (lane & 15);
    int colA = (lane >> 4) * 8;
    uint32_t aAh = smem_u32(&sAh[rowA][colA]);
    uint32_t aAl = smem_u32(&sAl[rowA][colA]);
    int rowB = wc * 64 + (lane & 7) + ((lane >> 4) << 3);
    int colB = ((lane >> 3) & 1) * 8;
    uint32_t aBh = smem_u32(&sBh[rowB][colB]);
    uint32_t aBl = smem_u32(&sBl[rowB][colB]);

    for (int kt = 0; kt < 2; kt++) {
        int k0 = kt * 32;
        #pragma unroll
        for (int it = 0; it < 2; it++) {
            int idx = tid + 256 * it;
            int row = idx >> 3, cg = (idx & 7) * 4;
            float4 va = *(const float4*)(g_q + (size_t)(hm0 + row) * (L_ * DH_) + (size_t)i * 64 + k0 + cg);
            cvt_store(va, &sAh[row][cg], &sAl[row][cg]);
        }
        #pragma unroll
        for (int it = 0; it < 8; it++) {
            int idx = tid + 256 * it;
            int row = idx >> 3, cg = (idx & 7) * 4;
            float4 vb = *(const float4*)(aKb + (size_t)row * 64 + k0 + cg);
            cvt_store(vb, &sBh[row][cg], &sBl[row][cg]);
        }
        __syncthreads();

        #pragma unroll
        for (int ks = 0; ks < 2; ks++) {
            uint32_t ah[2][4], al[2][4], bh[8][2], bl[8][2];
            #pragma unroll
            for (int mt = 0; mt < 2; mt++) {
                uint32_t off = (uint32_t)(mt * 16 * 40 + ks * 16) * 2;
                ldm_x4(ah[mt], aAh + off);
                ldm_x4(al[mt], aAl + off);
            }
            #pragma unroll
            for (int np = 0; np < 4; np++) {
                uint32_t off = (uint32_t)(np * 16 * 40 + ks * 16) * 2;
                uint32_t t[4];
                ldm_x4(t, aBh + off);
                bh[np * 2][0] = t[0]; bh[np * 2][1] = t[1];
                bh[np * 2 + 1][0] = t[2]; bh[np * 2 + 1][1] = t[3];
                ldm_x4(t, aBl + off);
                bl[np * 2][0] = t[0]; bl[np * 2][1] = t[1];
                bl[np * 2 + 1][0] = t[2]; bl[np * 2 + 1][1] = t[3];
            }
            #pragma unroll
            for (int mt = 0; mt < 2; mt++) {
                #pragma unroll
                for (int nt = 0; nt < 8; nt++) {
                    mma_bf16(acc[mt][nt], ah[mt], bh[nt]);
                    mma_bf16(acc[mt][nt], ah[mt], bl[nt]);
                    mma_bf16(acc[mt][nt], al[mt], bh[nt]);
                }
            }
        }
        __syncthreads();
    }

    // ---- Fused epilogue: e = S_e1 + scale*acc, then row softmax over j ----
    const float scale = 0.125f;
    #pragma unroll
    for (int mt = 0; mt < 2; mt++) {
        #pragma unroll
        for (int nt = 0; nt < 8; nt++) {
            int row = hm0 + wr * 32 + mt * 16 + (lane >> 2);
            int col = wc * 64 + nt * 8 + (lane & 3) * 2;
            const float* p = g_S + (size_t)row * (L_ * L_) + (size_t)i * 256 + col;
            float2 s0 = *(const float2*)p;
            float2 s1 = *(const float2*)(p + (size_t)8 * (L_ * L_));
            acc[mt][nt][0] = acc[mt][nt][0] * scale + s0.x;
            acc[mt][nt][1] = acc[mt][nt][1] * scale + s0.y;
            acc[mt][nt][2] = acc[mt][nt][2] * scale + s1.x;
            acc[mt][nt][3] = acc[mt][nt][3] * scale + s1.y;
        }
    }

    int rl[2][2];
    #pragma unroll
    for (int mt = 0; mt < 2; mt++)
        #pragma unroll
        for (int h = 0; h < 2; h++)
            rl[mt][h] = wr * 32 + mt * 16 + h * 8 + (lane >> 2);

    float mx[2][2];
    #pragma unroll
    for (int mt = 0; mt < 2; mt++)
        #pragma unroll
        for (int h = 0; h < 2; h++) {
            float m = -1e30f;
            #pragma unroll
            for (int nt = 0; nt < 8; nt++)
                m = fmaxf(m, fmaxf(acc[mt][nt][h * 2], acc[mt][nt][h * 2 + 1]));
            mx[mt][h] = m;
        }
    #pragma unroll
    for (int off = 1; off <= 2; off <<= 1) {
        #pragma unroll
        for (int mt = 0; mt < 2; mt++)
            #pragma unroll
            for (int h = 0; h < 2; h++)
                mx[mt][h] = fmaxf(mx[mt][h], __shfl_xor_sync(0xffffffffu, mx[mt][h], off));
    }
    if ((lane & 3) == 0) {
        #pragma unroll
        for (int mt = 0; mt < 2; mt++)
            #pragma unroll
            for (int h = 0; h < 2; h++)
                sRed[0][wc][rl[mt][h]] = mx[mt][h];
    }
    __syncthreads();
    float mfull[2][2];
    #pragma unroll
    for (int mt = 0; mt < 2; mt++)
        #pragma unroll
        for (int h = 0; h < 2; h++)
            mfull[mt][h] = fmaxf(fmaxf(sRed[0][0][rl[mt][h]], sRed[0][1][rl[mt][h]]),
                                 fmaxf(sRed[0][2][rl[mt][h]], sRed[0][3][rl[mt][h]]));

    float sm[2][2] = {{0.f, 0.f}, {0.f, 0.f}};
    #pragma unroll
    for (int mt = 0; mt < 2; mt++) {
        #pragma unroll
        for (int nt = 0; nt < 8; nt++) {
            #pragma unroll
            for (int h = 0; h < 2; h++) {
                float e0 = __expf(acc[mt][nt][h * 2] - mfull[mt][h]);
                float e1v = __expf(acc[mt][nt][h * 2 + 1] - mfull[mt][h]);
                acc[mt][nt][h * 2] = e0;
                acc[mt][nt][h * 2 + 1] = e1v;
                sm[mt][h] += e0 + e1v;
            }
        }
    }
    #pragma unroll
    for (int off = 1; off <= 2; off <<= 1) {
        #pragma unroll
        for (int mt = 0; mt < 2; mt++)
            #pragma unroll
            for (int h = 0; h < 2; h++)
                sm[mt][h] += __shfl_xor_sync(0xffffffffu, sm[mt][h], off);
    }
    if ((lane & 3) == 0) {
        #pragma unroll
        for (int mt = 0; mt < 2; mt++)
            #pragma unroll
            for (int h = 0; h < 2; h++)
                sRed[1][wc][rl[mt][h]] = sm[mt][h];
    }
    __syncthreads();
    float inv[2][2];
    #pragma unroll
    for (int mt = 0; mt < 2; mt++)
        #pragma unroll
        for (int h = 0; h < 2; h++) {
            float s = (sRed[1][0][rl[mt][h]] + sRed[1][1][rl[mt][h]]) +
                      (sRed[1][2][rl[mt][h]] + sRed[1][3][rl[mt][h]]);
            inv[mt][h] = 1.0f / s;
        }

    // write normalized probs to g_S
    #pragma unroll
    for (int mt = 0; mt < 2; mt++) {
        #pragma unroll
        for (int nt = 0; nt < 8; nt++) {
            int row = hm0 + wr * 32 + mt * 16 + (lane >> 2);
            int col = wc * 64 + nt * 8 + (lane & 3) * 2;
            float* p = g_S + (size_t)row * (L_ * L_) + (size_t)i * 256 + col;
            *(float2*)p = make_float2(acc[mt][nt][0] * inv[mt][0], acc[mt][nt][1] * inv[mt][0]);
            *(float2*)(p + (size_t)8 * (L_ * L_)) =
                make_float2(acc[mt][nt][2] * inv[mt][1], acc[mt][nt][3] * inv[mt][1]);
        }
    }
    __syncthreads();   // gmem writes visible block-wide before phase 2 reads

    // ---- Phase 2 (fused z2): z[hm0..+63, i, :] = alpha_tile @ aV[i] ----
    const float* aVb = aV + (size_t)i * (L_ * DH_);
    float accz[4][4];
    #pragma unroll
    for (int b = 0; b < 4; b++)
        #pragma unroll
        for (int c = 0; c < 4; c++) accz[b][c] = 0.f;

    int wrz = wid >> 1;
    int wdz = wid & 1;
    int rowAz = wrz * 16 + (lane & 15);
    uint32_t aAzh = smem_u32(&sAh[rowAz][colA]);
    uint32_t aAzl = smem_u32(&sAl[rowAz][colA]);
    int rowVt = lane & 15;
    int colVt = wdz * 32 + ((lane >> 4) << 3);
    uint32_t aVha = smem_u32(&sVh[rowVt][colVt]);
    uint32_t aVla = smem_u32(&sVl[rowVt][colVt]);

    for (int jc = 0; jc < 8; jc++) {
        int k0 = jc * 32;
        #pragma unroll
        for (int it = 0; it < 2; it++) {
            int idx = tid + 256 * it;
            int row = idx >> 3, cg = (idx & 7) * 4;
            float4 va = *(const float4*)(g_S + (size_t)(hm0 + row) * (L_ * L_) + (size_t)i * 256 + k0 + cg);
            cvt_store(va, &sAh[row][cg], &sAl[row][cg]);
        }
        #pragma unroll
        for (int it = 0; it < 2; it++) {
            int idx = tid + 256 * it;
            int jr = idx >> 4, cg = (idx & 15) * 4;
            float4 vb = *(const float4*)(aVb + (size_t)(k0 + jr) * 64 + cg);
            cvt_store(vb, &sVh[jr][cg], &sVl[jr][cg]);
        }
        __syncthreads();

        #pragma unroll
        for (int ks = 0; ks < 2; ks++) {
            uint32_t ah[4], al4[4], bh[4][2], bl[4][2];
            uint32_t offA = (uint32_t)(ks * 16) * 2;
            ldm_x4(ah, aAzh + offA);
            ldm_x4(al4, aAzl + offA);
            #pragma unroll
            for (int nn = 0; nn < 2; nn++) {
                uint32_t off = (uint32_t)(ks * 16 * 72 + nn * 16) * 2;
                uint32_t t[4];
                ldm_x4_trans(t, aVha + off);
                bh[nn * 2][0] = t[0]; bh[nn * 2][1] = t[1];
                bh[nn * 2 + 1][0] = t[2]; bh[nn * 2 + 1][1] = t[3];
                ldm_x4_trans(t, aVla + off);
                bl[nn * 2][0] = t[0]; bl[nn * 2][1] = t[1];
                bl[nn * 2 + 1][0] = t[2]; bl[nn * 2 + 1][1] = t[3];
            }
            #pragma unroll
            for (int nt = 0; nt < 4; nt++) {
                mma_bf16(accz[nt], ah, bh[nt]);
                mma_bf16(accz[nt], ah, bl[nt]);
                mma_bf16(accz[nt], al4, bh[nt]);
            }
        }
        __syncthreads();
    }

    #pragma unroll
    for (int nt = 0; nt < 4; nt++) {
        int row = hm0 + wrz * 16 + (lane >> 2);
        int col = wdz * 32 + nt * 8 + (lane & 3) * 2;
        float* p = g_z + (size_t)row * (L_ * DH_) + (size_t)i * 64 + col;
        *(float2*)p = make_float2(accz[nt][0], accz[nt][1]);
        *(float2*)(p + (size_t)8 * (L_ * DH_)) = make_float2(accz[nt][2], accz[nt][3]);
    }
}

// ---------------------------------------------------------------------------
// Kernel 4a: z += alpha @ v (RMW on top of fused-z2 output).
// grid (i-tiles=2, hm=512).
// ---------------------------------------------------------------------------
__global__ __launch_bounds__(256) void z1_mma_kernel()
{
    __shared__ __nv_bfloat16 sAh[128][40];
    __shared__ __nv_bfloat16 sAl[128][40];
    __shared__ __nv_bfloat16 sBh[32][72];
    __shared__ __nv_bfloat16 sBl[32][72];

    int tid = threadIdx.x;
    int lane = tid & 31, wid = tid >> 5;
    int wi = wid >> 1, wd = wid & 1;

    int i0 = blockIdx.x * 128;
    int hm = blockIdx.y;
    const float* Ab = g_S + (size_t)hm * (L_ * L_);
    const float* Bb = g_v + (size_t)hm * (L_ * DH_);

    float acc[2][4][4];
    #pragma unroll
    for (int a = 0; a < 2; a++)
        #pragma unroll
        for (int b = 0; b < 4; b++)
            #pragma unroll
            for (int c = 0; c < 4; c++) acc[a][b][c] = 0.f;

    int rowA = wi * 32 + (lane & 15);
    int colA = (lane >> 4) * 8;
    uint32_t aAh = smem_u32(&sAh[rowA][colA]);
    uint32_t aAl = smem_u32(&sAl[rowA][colA]);
    int rowBt = lane & 15;
    int colBt = wd * 32 + ((lane >> 4) << 3);
    uint32_t aBh = smem_u32(&sBh[rowBt][colBt]);
    uint32_t aBl = smem_u32(&sBl[rowBt][colBt]);

    for (int jt = 0; jt < 8; jt++) {
        int k0 = jt * 32;
        #pragma unroll
        for (int it = 0; it < 4; it++) {
            int idx = tid + 256 * it;
            int row = idx >> 3, cg = (idx & 7) * 4;
            float4 va = *(const float4*)(Ab + (size_t)(i0 + row) * 256 + k0 + cg);
            cvt_store(va, &sAh[row][cg], &sAl[row][cg]);
        }
        {
            int jr = tid >> 4, cg = (tid & 15) * 4;
            float4 vb = *(const float4*)(Bb + (size_t)(k0 + jr) * 64 + cg);
            cvt_store(vb, &sBh[jr][cg], &sBl[jr][cg]);
            int idx2 = tid + 256;
            int jr2 = idx2 >> 4, cg2 = (idx2 & 15) * 4;
            float4 vb2 = *(const float4*)(Bb + (size_t)(k0 + jr2) * 64 + cg2);
            cvt_store(vb2, &sBh[jr2][cg2], &sBl[jr2][cg2]);
        }
        __syncthreads();

        #pragma unroll
        for (int ks = 0; ks < 2; ks++) {
            uint32_t ah[2][4], al[2][4], bh[4][2], bl[4][2];
            #pragma unroll
            for (int mt = 0; mt < 2; mt++) {
                uint32_t off = (uint32_t)(mt * 16 * 40 + ks * 16) * 2;
                ldm_x4(ah[mt], aAh + off);
                ldm_x4(al[mt], aAl + off);
            }
            #pragma unroll
            for (int nn = 0; nn < 2; nn++) {
                uint32_t off = (uint32_t)(ks * 16 * 72 + nn * 16) * 2;
                uint32_t t[4];
                ldm_x4_trans(t, aBh + off);
                bh[nn * 2][0] = t[0]; bh[nn * 2][1] = t[1];
                bh[nn * 2 + 1][0] = t[2]; bh[nn * 2 + 1][1] = t[3];
                ldm_x4_trans(t, aBl + off);
                bl[nn * 2][0] = t[0]; bl[nn * 2][1] = t[1];
                bl[nn * 2 + 1][0] = t[2]; bl[nn * 2 + 1][1] = t[3];
            }
            #pragma unroll
            for (int mt = 0; mt < 2; mt++) {
                #pragma unroll
                for (int nt = 0; nt < 4; nt++) {
                    mma_bf16(acc[mt][nt], ah[mt], bh[nt]);
                    mma_bf16(acc[mt][nt], ah[mt], bl[nt]);
                    mma_bf16(acc[mt][nt], al[mt], bh[nt]);
                }
            }
        }
        __syncthreads();
    }

    float* Zb = g_z + (size_t)hm * (L_ * DH_);
    #pragma unroll
    for (int mt = 0; mt < 2; mt++) {
        #pragma unroll
        for (int nt = 0; nt < 4; nt++) {
            int row = i0 + wi * 32 + mt * 16 + (lane >> 2);
            int col = wd * 32 + nt * 8 + (lane & 3) * 2;
            float* p = Zb + (size_t)row * 64 + col;
            float2 o = *(float2*)p;
            o.x += acc[mt][nt][0]; o.y += acc[mt][nt][1];
            *(float2*)p = o;
            float* p2 = p + 8 * 64;
            float2 o2 = *(float2*)p2;
            o2.x += acc[mt][nt][2]; o2.y += acc[mt][nt][3];
            *(float2*)p2 = o2;
        }
    }
}

// ---------------------------------------------------------------------------
// Kernel 5: out[i, h*64+d] = sum_m z[(h*64+m), i, d]
// ---------------------------------------------------------------------------
__global__ __launch_bounds__(512) void reduce_kernel(float* __restrict__ out)
{
    int i = blockIdx.x;
    int e = threadIdx.x;
    int h = e >> 6, d = e & 63;
    const float* p = g_z + (h * 64) * (L_ * DH_) + i * DH_ + d;
    float s = 0.f;
    #pragma unroll 8
    for (int m = 0; m < 64; m++) s += p[m * (L_ * DH_)];
    out[i * 512 + e] = s;
}

// ---------------------------------------------------------------------------
extern "C" void kernel_launch(void* const* d_in, const int* in_sizes, int n_in,
                              void* d_out, int out_size)
{
    const float* x  = (const float*)d_in[0];
    const float* Wq = (const float*)d_in[1];
    const float* Wk = (const float*)d_in[2];
    const float* Wv = (const float*)d_in[3];
    const float* aK = (const float*)d_in[4];
    const float* aV = (const float*)d_in[5];
    float* out = (float*)d_out;

    static __nv_bfloat16 *xhi = nullptr, *xlo = nullptr, *whi = nullptr, *wlo = nullptr;
    if (!xhi) {
        cudaGetSymbolAddress((void**)&xhi, g_xhi);
        cudaGetSymbolAddress((void**)&xlo, g_xlo);
        cudaGetSymbolAddress((void**)&whi, g_whi);
        cudaGetSymbolAddress((void**)&wlo, g_wlo);
        cudaFuncSetAttribute(proj_mma_kernel,
                             cudaFuncAttributeMaxDynamicSharedMemorySize, PRJ_SMEM_TOTAL);
    }

    split_kernel<<<8192, 256>>>(x, xhi, xlo, 16384 * 512);
    split_kernel<<<256, 256>>>(Wq, whi, wlo, 512 * 512);
    split_kernel<<<256, 256>>>(Wk, whi + 512 * 512, wlo + 512 * 512, 512 * 512);
    split_kernel<<<256, 256>>>(Wv, whi + 2 * 512 * 512, wlo + 2 * 512 * 512, 512 * 512);

    proj_mma_kernel     <<<dim3(4, 128, 3), 256, PRJ_SMEM_TOTAL>>>();
    e1_mma_kernel       <<<dim3(2, 2, 512), 256>>>();
    e2_softmax_z2_kernel<<<dim3(8, 256), 256>>>(aK, aV);
    z1_mma_kernel       <<<dim3(2, 512), 256>>>();
    reduce_kernel       <<<dim3(L_), 512>>>(out);
}